// round 9
// baseline (speedup 1.0000x reference)
#include <cuda_runtime.h>
#include <math.h>

#define HH 1024
#define WW 1024
#define NPIX (HH * WW)
#define NWORDS (WW / 32)          // 32 packed words per row
#define RPB 8                     // rows per block in kernel A

// kernel B tiling
#define CTILE 32                  // columns per block (one mask word)
#define RTILE 256                 // rows per block
#define HALO  32                  // in-shared scan band beyond the tile
#define SROWS (RTILE + 2 * HALO)  // 320 shared rows
#define DUNROLL 6                 // branch-free scan depth (<= HALO)
#define NB_C (WW / CTILE)         // 32
#define NB_R (HH / RTILE)         // 4
#define TOT_B_BLOCKS (NB_C * NB_R * 2)   // 256

// Scratch (no allocations allowed anywhere)
__device__ unsigned int g_edgebits[2][HH * NWORDS];   // 256 KB
__device__ float        g_g2[2][NPIX];                // 8 MB
__device__ float        g_blockSums[TOT_B_BLOCKS];

__device__ __forceinline__ unsigned horiz3(unsigned wv, unsigned wl, unsigned wr) {
    return wv & ((wv << 1) | (wl >> 31)) & ((wv >> 1) | (wr << 31));
}

// ---------------------------------------------------------------------------
// Kernel A: bit-packed edges + per-row 1D distance, RPB rows per block.
// 64-bit window around each pixel; the fallback (window empty on either side)
// is decided PER-WARP via __any_sync, so interior warps run a straight-line
// hot path with no divergent regions. Border warps take the exact slow path
// (incl. the reference's 1e6 fp32 defaults).
// ---------------------------------------------------------------------------
__global__ void __launch_bounds__(WW) edges_rowdist_kernel(
    const float* __restrict__ preds, const float* __restrict__ targets)
{
    const int r0 = blockIdx.x * RPB;
    const int m  = blockIdx.y;
    const int j  = threadIdx.x;
    const float* __restrict__ seg = (m == 0) ? preds : targets;

    __shared__ unsigned shB[RPB + 2][NWORDS];
    __shared__ unsigned shE[RPB][NWORDS];

    const int t = j >> 5, k = j & 31;

    // load RPB+2 rows (batched for MLP), ballot-pack to bits
    float v[RPB + 2];
    #pragma unroll
    for (int rr = 0; rr < RPB + 2; rr++) {
        const int row = r0 + rr - 1;
        v[rr] = (row >= 0 && row < HH) ? seg[row * WW + j] : 0.0f;
    }
    #pragma unroll
    for (int rr = 0; rr < RPB + 2; rr++) {
        const unsigned b = __ballot_sync(0xffffffffu, v[rr] == 1.0f);
        if (k == 0) shB[rr][t] = b;
    }
    __syncthreads();

    // RPB*NWORDS = 256 threads compute one edge word each
    if (j < RPB * NWORDS) {
        const int w  = j & (NWORDS - 1);
        const int rr = j >> 5;            // NWORDS == 32
        const unsigned hp = horiz3(shB[rr][w],
                                   w > 0 ? shB[rr][w - 1] : 0u,
                                   w < NWORDS - 1 ? shB[rr][w + 1] : 0u);
        const unsigned hc = horiz3(shB[rr + 1][w],
                                   w > 0 ? shB[rr + 1][w - 1] : 0u,
                                   w < NWORDS - 1 ? shB[rr + 1][w + 1] : 0u);
        const unsigned hn = horiz3(shB[rr + 2][w],
                                   w > 0 ? shB[rr + 2][w - 1] : 0u,
                                   w < NWORDS - 1 ? shB[rr + 2][w + 1] : 0u);
        const unsigned e = shB[rr + 1][w] & ~(hp & hc & hn);
        shE[rr][w] = e;
        g_edgebits[m][(r0 + rr) * NWORDS + w] = e;
    }
    __syncthreads();

    // per-pixel nearest edge bit in each of the RPB rows
    #pragma unroll
    for (int rr = 0; rr < RPB; rr++) {
        const unsigned wc = shE[rr][t];
        const unsigned wl = (t > 0)          ? shE[rr][t - 1] : 0u;
        const unsigned wr = (t < NWORDS - 1) ? shE[rr][t + 1] : 0u;

        const unsigned long long L = ((unsigned long long)wc << 32) | wl; // pixel at bit 32+k
        const unsigned long long R = ((unsigned long long)wr << 32) | wc; // pixel at bit k
        const unsigned long long lm = L & (~0ULL >> (31 - k));  // bits <= pixel pos
        const unsigned long long rm = R & (~0ULL << k);         // bits >= pixel pos

        float g;
        if (!__any_sync(0xffffffffu, (lm == 0ULL) | (rm == 0ULL))) {
            // warp-uniform hot path: straight line, edge pixels give 0
            const int dl = __clzll((long long)lm) - (31 - k);
            const int dr = __ffsll((long long)rm) - 1 - k;
            g = (float)min(dl, dr);          // far below the 1e6 cap
        } else {
            // border warps / nearly-empty rows — full exact logic
            float dl, dr;
            if (lm) {
                dl = (float)(__clzll((long long)lm) - (31 - k));
            } else {
                int tt = t - 2;
                while (tt >= 0 && shE[rr][tt] == 0u) tt--;
                if (tt >= 0) dl = (float)(j - (tt * 32 + (31 - __clz(shE[rr][tt]))));
                else         dl = (float)j + 1e6f;      // reference default, exact fp32
            }
            if (rm) {
                dr = (float)(__ffsll((long long)rm) - 1 - k);
            } else {
                int tt = t + 2;
                while (tt < NWORDS && shE[rr][tt] == 0u) tt++;
                if (tt < NWORDS) dr = (float)((tt * 32 + (__ffs(shE[rr][tt]) - 1)) - j);
                else             dr = 1e6f - (float)j;  // reference default, exact fp32
            }
            g = fminf(fminf(dl, dr), 1e6f);
        }
        g_g2[m][(r0 + rr) * WW + j] = g * g;
    }
}

// ---------------------------------------------------------------------------
// Kernel B: column lower-envelope in shared-memory tiles (32 cols x 256 rows
// + 32-row halo staged to LDS; OOB rows hold 3e37 and can never win).
// The scan is a BRANCH-FREE unrolled d=1..DUNROLL sweep: no exit tests, no
// bounds checks, warp-uniform conflict-free LDS rows. Exact because extra
// candidates are >= the true min, and (DUNROLL+1)^2 >= best afterwards proves
// no farther row can improve. A ballot-guarded exact continuation handles the
// rare remainder. Mask applied as a multiply. Deterministic reduction.
// ---------------------------------------------------------------------------
__global__ void __launch_bounds__(1024) colpass_kernel()
{
    const int c0 = blockIdx.x * CTILE;
    const int t0 = blockIdx.y * RTILE;
    const int m  = blockIdx.z;

    __shared__ float    sh[SROWS][CTILE];
    __shared__ unsigned shM[RTILE];

    const int tid = threadIdx.x;
    const int c   = tid & 31;        // column within tile
    const int rg  = tid >> 5;        // 0..31
    const float* __restrict__ g2 = g_g2[m];

    // stage g2 tile + halo (coalesced; OOB -> 3e37 sentinel)
    #pragma unroll
    for (int rr = rg; rr < SROWS; rr += 32) {
        const int row = t0 - HALO + rr;
        sh[rr][c] = (row >= 0 && row < HH) ? g2[row * WW + c0 + c] : 3e37f;
    }
    if (tid < RTILE)
        shM[tid] = g_edgebits[1 - m][(t0 + tid) * NWORDS + (c0 >> 5)];
    __syncthreads();

    float acc = 0.0f;
    #pragma unroll
    for (int q = 0; q < RTILE / 32; q++) {
        const int rl = rg + 32 * q;          // row within tile
        const int sr = rl + HALO;            // shared row (HALO..HALO+RTILE-1)
        const unsigned mbit = (shM[rl] >> c) & 1u;

        float best = sh[sr][c];
        #pragma unroll
        for (int d = 1; d <= DUNROLL; d++) {
            // sr-d >= HALO-DUNROLL >= 0, sr+d <= HALO+RTILE-1+DUNROLL < SROWS
            best = fminf(best,
                         fminf(sh[sr - d][c], sh[sr + d][c]) + (float)(d * d));
        }

        // rare exact continuation: only if a masked lane is unresolved
        const float next2 = (float)((DUNROLL + 1) * (DUNROLL + 1));
        if (__any_sync(0xffffffffu, mbit && (next2 < best))) {
            if (mbit && (next2 < best)) {
                const int r = t0 + rl;       // global row
                int d = DUNROLL + 1;
                while ((float)(d * d) < best) {
                    const float vu = (sr - d >= 0)
                        ? sh[sr - d][c]
                        : ((r - d >= 0) ? g2[(r - d) * WW + c0 + c] : 3e37f);
                    const float vd = (sr + d < SROWS)
                        ? sh[sr + d][c]
                        : ((r + d < HH) ? g2[(r + d) * WW + c0 + c] : 3e37f);
                    best = fminf(best, fminf(vu, vd) + (float)(d * d));
                    d++;
                    if (r - d < 0 && r + d >= HH) break;
                }
            }
        }
        acc += (float)mbit * sqrtf(best);
    }

    // deterministic in-block reduction
    float s = acc;
    #pragma unroll
    for (int o = 16; o > 0; o >>= 1) s += __shfl_down_sync(0xffffffffu, s, o);

    __shared__ float warpsum[32];
    if (c == 0) warpsum[rg] = s;
    __syncthreads();

    if (tid < 32) {
        float w = warpsum[tid];
        #pragma unroll
        for (int o = 16; o > 0; o >>= 1) w += __shfl_down_sync(0xffffffffu, w, o);
        if (tid == 0)
            g_blockSums[(m * NB_R + blockIdx.y) * NB_C + blockIdx.x] = w;
    }
}

// ---------------------------------------------------------------------------
// Kernel C: deterministic final reduction + sigmoid.
// ---------------------------------------------------------------------------
__global__ void __launch_bounds__(256) finalize_kernel(float* __restrict__ out)
{
    __shared__ float sh[256];
    sh[threadIdx.x] = g_blockSums[threadIdx.x];   // TOT_B_BLOCKS == 256
    __syncthreads();
    #pragma unroll
    for (int stride = 128; stride > 0; stride >>= 1) {
        if (threadIdx.x < stride) sh[threadIdx.x] += sh[threadIdx.x + stride];
        __syncthreads();
    }
    if (threadIdx.x == 0) {
        const float loss = sh[0] / (2.0f * (float)NPIX);
        out[0] = 1.0f / (1.0f + expf(-loss));
    }
}

// ---------------------------------------------------------------------------
extern "C" void kernel_launch(void* const* d_in, const int* in_sizes, int n_in,
                              void* d_out, int out_size)
{
    const float* preds   = (const float*)d_in[0];
    const float* targets = (const float*)d_in[1];
    float* out = (float*)d_out;
    (void)in_sizes; (void)n_in; (void)out_size;

    dim3 gridA(HH / RPB, 2);
    edges_rowdist_kernel<<<gridA, WW>>>(preds, targets);

    dim3 gridB(NB_C, NB_R, 2);
    colpass_kernel<<<gridB, 1024>>>();

    finalize_kernel<<<1, 256>>>(out);
}

// round 10
// speedup vs baseline: 1.1655x; 1.1655x over previous
#include <cuda_runtime.h>
#include <math.h>

#define HH 1024
#define WW 1024
#define NPIX (HH * WW)
#define NWORDS (WW / 32)          // 32 packed words per row
#define RPB 8                     // rows per block in kernel A

// kernel B tiling
#define CTILE 32                  // columns per block (one mask word)
#define RTILE 256                 // rows per block
#define HALO  32                  // in-shared scan band beyond the tile
#define SROWS (RTILE + 2 * HALO)  // 320 shared rows
#define NB_C (WW / CTILE)         // 32
#define NB_R (HH / RTILE)         // 4
#define TOT_B_BLOCKS (NB_C * NB_R * 2)   // 512 total (x,y,z grid) -> see launch
#define FIXSCALE 1048576.0f       // 2^20 fixed point

// Scratch (no allocations allowed anywhere)
__device__ unsigned int       g_edgebits[2][HH * NWORDS];   // 256 KB
__device__ float              g_g2[2][NPIX];                // 8 MB
__device__ unsigned long long g_acc;   // [63:48] block count, [47:0] fixed-point sum

__device__ __forceinline__ unsigned horiz3(unsigned wv, unsigned wl, unsigned wr) {
    return wv & ((wv << 1) | (wl >> 31)) & ((wv >> 1) | (wr << 31));
}

// ---------------------------------------------------------------------------
// Kernel A: bit-packed edges + per-row 1D distance, RPB rows per block.
// (R6 version verbatim — fastest measured variant.)
// ---------------------------------------------------------------------------
__global__ void __launch_bounds__(WW) edges_rowdist_kernel(
    const float* __restrict__ preds, const float* __restrict__ targets)
{
    const int r0 = blockIdx.x * RPB;
    const int m  = blockIdx.y;
    const int j  = threadIdx.x;
    const float* __restrict__ seg = (m == 0) ? preds : targets;

    // reset the packed accumulator for this replay (stream-ordered before B)
    if (blockIdx.x == 0 && m == 0 && j == 0) g_acc = 0ULL;

    __shared__ unsigned shB[RPB + 2][NWORDS];
    __shared__ unsigned shE[RPB][NWORDS];

    const int t = j >> 5, k = j & 31;

    // load RPB+2 rows (batched for MLP), ballot-pack to bits
    float v[RPB + 2];
    #pragma unroll
    for (int rr = 0; rr < RPB + 2; rr++) {
        const int row = r0 + rr - 1;
        v[rr] = (row >= 0 && row < HH) ? seg[row * WW + j] : 0.0f;
    }
    #pragma unroll
    for (int rr = 0; rr < RPB + 2; rr++) {
        const unsigned b = __ballot_sync(0xffffffffu, v[rr] == 1.0f);
        if (k == 0) shB[rr][t] = b;
    }
    __syncthreads();

    // RPB*NWORDS = 256 threads compute one edge word each
    if (j < RPB * NWORDS) {
        const int w  = j & (NWORDS - 1);
        const int rr = j >> 5;            // NWORDS == 32
        const unsigned hp = horiz3(shB[rr][w],
                                   w > 0 ? shB[rr][w - 1] : 0u,
                                   w < NWORDS - 1 ? shB[rr][w + 1] : 0u);
        const unsigned hc = horiz3(shB[rr + 1][w],
                                   w > 0 ? shB[rr + 1][w - 1] : 0u,
                                   w < NWORDS - 1 ? shB[rr + 1][w + 1] : 0u);
        const unsigned hn = horiz3(shB[rr + 2][w],
                                   w > 0 ? shB[rr + 2][w - 1] : 0u,
                                   w < NWORDS - 1 ? shB[rr + 2][w + 1] : 0u);
        const unsigned e = shB[rr + 1][w] & ~(hp & hc & hn);
        shE[rr][w] = e;
        g_edgebits[m][(r0 + rr) * NWORDS + w] = e;
    }
    __syncthreads();

    // per-pixel nearest edge bit in each of the RPB rows (clz/ffs, exact)
    #pragma unroll
    for (int rr = 0; rr < RPB; rr++) {
        const unsigned ew = shE[rr][t];
        float g;
        if ((ew >> k) & 1u) {
            g = 0.0f;
        } else {
            float dl;
            const unsigned lw = (k > 0) ? (ew & ((1u << k) - 1u)) : 0u;
            if (lw) {
                dl = (float)(k - (31 - __clz(lw)));
            } else {
                int tt = t - 1;
                while (tt >= 0 && shE[rr][tt] == 0u) tt--;
                if (tt >= 0) dl = (float)(j - (tt * 32 + (31 - __clz(shE[rr][tt]))));
                else         dl = (float)j + 1e6f;      // reference default, exact fp32
            }
            float dr;
            const unsigned rw = (k < 31) ? (ew & (0xFFFFFFFEu << k)) : 0u;
            if (rw) {
                dr = (float)(__ffs(rw) - 1 - k);
            } else {
                int tt = t + 1;
                while (tt < NWORDS && shE[rr][tt] == 0u) tt++;
                if (tt < NWORDS) dr = (float)((tt * 32 + (__ffs(shE[rr][tt]) - 1)) - j);
                else             dr = 1e6f - (float)j;  // reference default, exact fp32
            }
            g = fminf(fminf(dl, dr), 1e6f);
        }
        g_g2[m][(r0 + rr) * WW + j] = g * g;
    }
}

// ---------------------------------------------------------------------------
// Kernel B: column lower-envelope in shared-memory tiles (R6 loop verbatim),
// with the final reduction fused via ONE packed u64 atomic:
//   value = (1 << 48) | round(block_sum * 2^20)
// A single atomic is totally ordered, so the block seeing old_count == N-1
// has the complete total (old_sum + own) — no fences, no extra kernel,
// integer adds -> bit-deterministic. That block writes sigmoid(loss).
// ---------------------------------------------------------------------------
__global__ void __launch_bounds__(1024) colpass_kernel(float* __restrict__ out)
{
    const int c0 = blockIdx.x * CTILE;
    const int t0 = blockIdx.y * RTILE;
    const int m  = blockIdx.z;

    __shared__ float    sh[SROWS][CTILE];
    __shared__ unsigned shM[RTILE];

    const int tid = threadIdx.x;
    const int c   = tid & 31;        // column within tile
    const int rg  = tid >> 5;        // 0..31
    const float* __restrict__ g2 = g_g2[m];

    // stage g2 tile + halo (coalesced: each warp loads one 128B row stripe)
    #pragma unroll
    for (int rr = rg; rr < SROWS; rr += 32) {
        const int row = t0 - HALO + rr;
        sh[rr][c] = (row >= 0 && row < HH) ? g2[row * WW + c0 + c] : 3e37f;
    }
    if (tid < RTILE)
        shM[tid] = g_edgebits[1 - m][(t0 + tid) * NWORDS + (c0 >> 5)];
    __syncthreads();

    float acc = 0.0f;
    #pragma unroll
    for (int q = 0; q < RTILE / 32; q++) {
        const int rl = rg + 32 * q;          // row within tile
        if ((shM[rl] >> c) & 1u) {
            const int r  = t0 + rl;          // global row
            const int sr = rl + HALO;        // shared row index
            float best = sh[sr][c];
            int d = 1;
            while ((float)(d * d) < best) {  // exact prune
                const float vu = (sr - d >= 0)
                    ? sh[sr - d][c]
                    : ((r - d >= 0) ? g2[(r - d) * WW + c0 + c] : 3e37f);
                const float vd = (sr + d < SROWS)
                    ? sh[sr + d][c]
                    : ((r + d < HH) ? g2[(r + d) * WW + c0 + c] : 3e37f);
                best = fminf(best, fminf(vu, vd) + (float)(d * d));
                d++;
                if (r - d < 0 && r + d >= HH) break;
            }
            acc += sqrtf(best);
        }
    }

    // deterministic in-block reduction
    float s = acc;
    #pragma unroll
    for (int o = 16; o > 0; o >>= 1) s += __shfl_down_sync(0xffffffffu, s, o);

    __shared__ float warpsum[32];
    if (c == 0) warpsum[rg] = s;
    __syncthreads();

    if (tid == 0) {
        float w = 0.0f;
        #pragma unroll
        for (int i = 0; i < 32; i++) w += warpsum[i];   // fixed order, deterministic

        // pack: high 16 bits = block count (1), low 48 bits = fixed-point sum
        const unsigned long long vfix =
            (unsigned long long)__float2ull_rn(w * FIXSCALE);
        const unsigned long long packed = (1ULL << 48) | vfix;
        const unsigned long long old = atomicAdd(&g_acc, packed);

        const int nblocks = NB_C * NB_R * 2;            // 256
        if ((old >> 48) == (unsigned long long)(nblocks - 1)) {
            const unsigned long long total =
                (old & 0xFFFFFFFFFFFFULL) + vfix;
            const float loss =
                (float)((double)total * (1.0 / (double)FIXSCALE))
                / (2.0f * (float)NPIX);
            out[0] = 1.0f / (1.0f + expf(-loss));
        }
    }
}

// ---------------------------------------------------------------------------
extern "C" void kernel_launch(void* const* d_in, const int* in_sizes, int n_in,
                              void* d_out, int out_size)
{
    const float* preds   = (const float*)d_in[0];
    const float* targets = (const float*)d_in[1];
    float* out = (float*)d_out;
    (void)in_sizes; (void)n_in; (void)out_size;

    dim3 gridA(HH / RPB, 2);
    edges_rowdist_kernel<<<gridA, WW>>>(preds, targets);

    dim3 gridB(NB_C, NB_R, 2);
    colpass_kernel<<<gridB, 1024>>>(out);
}